// round 17
// baseline (speedup 1.0000x reference)
#include <cuda_runtime.h>
#include <math.h>

// Moebius transform on 3-D blocks + log|det J| row reduction.
// Variant: 128 threads/CTA, 24 floats (8 blocks of 3) per thread ->
// 12 front-batched LDG.128 per thread, doubling per-warp MLP depth vs the
// 256x12 configuration (which sits at the 302 MB/replay DRAM floor).
// Determinant via conformal-map closed form: |det J| = c^2 * |yn . Hn|,
// c = (1-|w|^2)/|n+w|^2, Hn = n - 2 p (n.p)/|p|^2 (Householder image of n);
// one __logf of the product of 8 block dets per thread.

__device__ __forceinline__ float moebius_block3(
    float a0, float a1, float a2,     // x block
    float v0, float v1, float v2,     // w block
    float& y0, float& y1, float& y2)  // y block out
{
    // radial normalization
    float xns   = fmaf(a0, a0, fmaf(a1, a1, a2 * a2));
    float inv   = rsqrtf(xns);
    float xnorm = xns * inv;                 // sqrt(xns)

    float n0 = a0 * inv, n1 = a1 * inv, n2 = a2 * inv;
    float p0 = n0 + v0,  p1 = n1 + v1,  p2 = n2 + v2;   // n + w

    float wns  = fmaf(v0, v0, fmaf(v1, v1, v2 * v2));
    float pns  = fmaf(p0, p0, fmaf(p1, p1, p2 * p2));
    float invp = __frcp_rn(pns);
    float c    = (1.0f - wns) * invp;

    float yn0 = fmaf(c, p0, v0);
    float yn1 = fmaf(c, p1, v1);
    float yn2 = fmaf(c, p2, v2);

    y0 = xnorm * yn0;
    y1 = xnorm * yn1;
    y2 = xnorm * yn2;

    // |det J| = c^2 * | yn . (n - 2 p (n.p)/|p|^2) |
    float np = fmaf(n0, p0, fmaf(n1, p1, n2 * p2));
    float t  = 2.0f * np * invp;
    float h0 = fmaf(-t, p0, n0);
    float h1 = fmaf(-t, p1, n1);
    float h2 = fmaf(-t, p2, n2);
    float d  = fmaf(yn0, h0, fmaf(yn1, h1, yn2 * h2));

    return c * c * fabsf(d);
}

__global__ void __launch_bounds__(128)
moebius_kernel(const float* __restrict__ x,
               const float* __restrict__ w,
               float* __restrict__ y,
               float* __restrict__ logdet,
               int F)
{
    const int row  = blockIdx.x;
    const int t    = threadIdx.x;
    const int base = row * F + t * 24;           // B*F < 2^31, fits int

    // 6x float4 streaming loads of x and w each, all front-batched
    // (24 floats = 8 blocks of 3 per thread).
    const float4* xv = reinterpret_cast<const float4*>(x + base);
    const float4* wv = reinterpret_cast<const float4*>(w + base);
    float4 x0 = __ldcs(xv + 0), x1 = __ldcs(xv + 1), x2 = __ldcs(xv + 2);
    float4 x3 = __ldcs(xv + 3), x4 = __ldcs(xv + 4), x5 = __ldcs(xv + 5);
    float4 w0 = __ldcs(wv + 0), w1 = __ldcs(wv + 1), w2 = __ldcs(wv + 2);
    float4 w3 = __ldcs(wv + 3), w4 = __ldcs(wv + 4), w5 = __ldcs(wv + 5);

    float xs[24] = {x0.x, x0.y, x0.z, x0.w, x1.x, x1.y, x1.z, x1.w,
                    x2.x, x2.y, x2.z, x2.w, x3.x, x3.y, x3.z, x3.w,
                    x4.x, x4.y, x4.z, x4.w, x5.x, x5.y, x5.z, x5.w};
    float ws[24] = {w0.x, w0.y, w0.z, w0.w, w1.x, w1.y, w1.z, w1.w,
                    w2.x, w2.y, w2.z, w2.w, w3.x, w3.y, w3.z, w3.w,
                    w4.x, w4.y, w4.z, w4.w, w5.x, w5.y, w5.z, w5.w};
    float ys[24];

    float prod = 1.0f;
#pragma unroll
    for (int k = 0; k < 8; k++) {
        prod *= moebius_block3(xs[3*k], xs[3*k+1], xs[3*k+2],
                               ws[3*k], ws[3*k+1], ws[3*k+2],
                               ys[3*k], ys[3*k+1], ys[3*k+2]);
    }

    float4* yv = reinterpret_cast<float4*>(y + base);
    __stcs(yv + 0, make_float4(ys[0],  ys[1],  ys[2],  ys[3]));
    __stcs(yv + 1, make_float4(ys[4],  ys[5],  ys[6],  ys[7]));
    __stcs(yv + 2, make_float4(ys[8],  ys[9],  ys[10], ys[11]));
    __stcs(yv + 3, make_float4(ys[12], ys[13], ys[14], ys[15]));
    __stcs(yv + 4, make_float4(ys[16], ys[17], ys[18], ys[19]));
    __stcs(yv + 5, make_float4(ys[20], ys[21], ys[22], ys[23]));

    // log of product of the 8 |det|s: one fast log per thread.
    // c^2 in [~0.1, 9], d bounded; product of 8 stays in fp32 range.
    float acc = __logf(prod);

    // Reduce acc over the CTA (one row) — warp shuffle then shared.
#pragma unroll
    for (int o = 16; o > 0; o >>= 1)
        acc += __shfl_xor_sync(0xffffffffu, acc, o);

    __shared__ float ssum[4];
    const int lane = t & 31;
    const int warp = t >> 5;
    if (lane == 0) ssum[warp] = acc;
    __syncthreads();

    if (warp == 0) {
        float s = (lane < 4) ? ssum[lane] : 0.0f;
#pragma unroll
        for (int o = 2; o > 0; o >>= 1)
            s += __shfl_xor_sync(0xffffffffu, s, o);
        if (lane == 0) logdet[row] = s;
    }
}

extern "C" void kernel_launch(void* const* d_in, const int* in_sizes, int n_in,
                              void* d_out, int out_size)
{
    const float* x = (const float*)d_in[0];
    const float* w = (const float*)d_in[1];
    float* out = (float*)d_out;

    const int total = in_sizes[0];          // B * F
    const int batch = out_size - total;     // out = y (B*F) ++ logdet (B)
    const int F     = total / batch;        // 3072

    float* y      = out;
    float* logdet = out + (size_t)total;

    const int threads = F / 24;             // 128: 8 blocks of 3 per thread
    moebius_kernel<<<batch, threads>>>(x, w, y, logdet, F);
}